// round 10
// baseline (speedup 1.0000x reference)
#include <cuda_runtime.h>
#include <cstdint>

#define N_NODES 30000
#define N_EDGES 480000
#define IN_FEAT 256
#define OUT_FEAT 256
#define N_RELS 8
#define N_HEADS 4
#define HEAD_DIM 64
#define CAP 64                      // max in-degree bin (Poisson(16): P(>=64) ~ 1e-18)
#define NKT 8                       // 256 / 32 K-tiles

// -------- scratch (static device globals; no allocations allowed) --------
__device__ float g_feat[(size_t)N_RELS * N_NODES * OUT_FEAT];   // [r][n][h*64+d]
__device__ float g_el[N_RELS * N_NODES * N_HEADS];              // [r][n][h]
__device__ float g_er[N_RELS * N_NODES * N_HEADS];
__device__ int   g_counts[N_NODES];
__device__ int   g_perm[(size_t)N_NODES * CAP];

__device__ __forceinline__ uint32_t f2tf(float f) {
    uint32_t u;
    asm("cvt.rna.tf32.f32 %0, %1;" : "=r"(u) : "f"(f));
    return u;
}

__device__ __forceinline__ void mma_tf32(float c[4], const uint32_t a[4], const uint32_t b[2]) {
    asm volatile(
        "mma.sync.aligned.m16n8k8.row.col.f32.tf32.tf32.f32 "
        "{%0,%1,%2,%3}, {%4,%5,%6,%7}, {%8,%9}, {%0,%1,%2,%3};"
        : "+f"(c[0]), "+f"(c[1]), "+f"(c[2]), "+f"(c[3])
        : "r"(a[0]), "r"(a[1]), "r"(a[2]), "r"(a[3]), "r"(b[0]), "r"(b[1]));
}

__device__ __forceinline__ float lrelu(float x) { return x >= 0.f ? x : 0.2f * x; }

// ---------------------------------------------------------------------------
// Kernel 1: GEMM  C[128 x 128] per CTA  (rowblock, rel*headpair)
//   feat_all[r][n][h*64+d] = sum_i inputs[n][i] * W[r][h][i][d]
// tf32 mma.sync m16n8k8. BM=128 BN=128 BK=32, 8 warps; warp = 32 rows x 64 cols
// (= one head). Single smem buffer + register staging (R2 structure, measured
// best). NEW: permuted smem layouts so fragment loads are LDS.128:
//   A[row][k] stored at sA[row][(k&3)*8 + (k>>2)]  (stride 36, conflict-free)
//   B stored per-consumer-lane chunks of 68 words   (conflict-free)
// Hot-loop loads per warp per K-tile: 24 LDS.128 (was 96 LDS.32).
// ---------------------------------------------------------------------------
__global__ __launch_bounds__(256, 2) void gemm_kernel(
    const float* __restrict__ A,        // [N_NODES, 256]
    const float* __restrict__ W,        // [8,4,256,64]
    const float* __restrict__ attn_l,   // [8,4,64]
    const float* __restrict__ attn_r)   // [8,4,64]
{
    __shared__ uint32_t sA[128][36];    // 18432 B
    __shared__ uint32_t sB[2][32 * 68]; // 17408 B; [wn][chunk(lane)*68 + u*8 + jj]

    const int r  = blockIdx.y >> 1;
    const int hp = blockIdx.y & 1;      // head pair: heads {2hp, 2hp+1}
    const int rowBase = blockIdx.x * 128;
    const int tid = threadIdx.x;
    const int warp = tid >> 5, lane = tid & 31;
    const int warp_m = warp >> 1;       // 0..3 (row group of 32)
    const int warp_n = warp & 1;        // 0..1 (head within pair)
    const int g = lane >> 2, t = lane & 3;

    const float* Wbase = W + (size_t)(r * 4 + hp * 2) * IN_FEAT * HEAD_DIM;

    float c[2][8][4];
#pragma unroll
    for (int m = 0; m < 2; m++)
#pragma unroll
        for (int j = 0; j < 8; j++)
#pragma unroll
            for (int q = 0; q < 4; q++) c[m][j][q] = 0.f;

    // staging registers for the next K-tile
    float4 ar[4], br[4];

    auto ldA = [&](int k0) {
#pragma unroll
        for (int i = 0; i < 4; i++) {
            int idx = tid + i * 256;
            int row = idx >> 3, c4 = (idx & 7) << 2;
            int gr = rowBase + row;
            ar[i] = (gr < N_NODES)
                  ? *(const float4*)(A + (size_t)gr * IN_FEAT + k0 + c4)
                  : make_float4(0.f, 0.f, 0.f, 0.f);
        }
    };
    auto ldB = [&](int k0) {
#pragma unroll
        for (int i = 0; i < 4; i++) {
            int idx = tid + i * 256;
            int k = idx >> 5, c4g = idx & 31;
            int col = c4g << 2;
            int head = col >> 6, d = col & 63;
            br[i] = *(const float4*)(Wbase + (size_t)head * (IN_FEAT * HEAD_DIM)
                                     + (size_t)(k0 + k) * HEAD_DIM + d);
        }
    };
    // commit staged registers to PERMUTED smem layouts (tf32-convert at store)
    auto commit = [&]() {
#pragma unroll
        for (int i = 0; i < 4; i++) {
            int idx = tid + i * 256;
            int row = idx >> 3, a4 = idx & 7;     // k values 4*a4 .. 4*a4+3
            sA[row][a4 +  0] = f2tf(ar[i].x);     // perm(k) = (k&3)*8 + k/4
            sA[row][a4 +  8] = f2tf(ar[i].y);
            sA[row][a4 + 16] = f2tf(ar[i].z);
            sA[row][a4 + 24] = f2tf(ar[i].w);
        }
#pragma unroll
        for (int i = 0; i < 4; i++) {
            int idx = tid + i * 256;
            int k = idx >> 5, col = (idx & 31) << 2;
            int wn = col >> 6, lc = col & 63;
            int jj = lc >> 3, g0 = lc & 7;        // g0 in {0,4}; cols -> chunks g0..g0+3
            int tt = k & 3, u = k >> 2;
            uint32_t* p = &sB[wn][(g0 * 4 + tt) * 68 + u * 8 + jj];
            p[0]       = f2tf(br[i].x);           // chunk (g0+0)*4+tt
            p[272]     = f2tf(br[i].y);           // chunk (g0+1)*4+tt  (+4*68)
            p[544]     = f2tf(br[i].z);
            p[816]     = f2tf(br[i].w);
        }
    };

    ldA(0); ldB(0);
    commit();
    __syncthreads();

    const int R0 = warp_m * 32 + g;
    const uint32_t* bp = &sB[warp_n][lane * 68];  // this lane's 68-word chunk

#pragma unroll 1
    for (int k = 0; k < NKT; k++) {
        const bool has_next = (k + 1) < NKT;
        if (has_next) { ldA((k + 1) * 32); ldB((k + 1) * 32); }  // overlap with mma

#pragma unroll
        for (int h = 0; h < 2; h++) {             // half: ks {0,1} then {2,3}
            uint4 av[4];                          // rows R0, R0+8, R0+16, R0+24
            av[0] = *(const uint4*)&sA[R0     ][t * 8 + h * 4];
            av[1] = *(const uint4*)&sA[R0 +  8][t * 8 + h * 4];
            av[2] = *(const uint4*)&sA[R0 + 16][t * 8 + h * 4];
            av[3] = *(const uint4*)&sA[R0 + 24][t * 8 + h * 4];
#pragma unroll
            for (int kss = 0; kss < 2; kss++) {
                const int ks = h * 2 + kss;
                uint4 b0 = *(const uint4*)(bp + ks * 16);       // b[0..3][0]
                uint4 b1 = *(const uint4*)(bp + ks * 16 + 4);   // b[4..7][0]
                uint4 b2 = *(const uint4*)(bp + ks * 16 + 8);   // b[0..3][1]
                uint4 b3 = *(const uint4*)(bp + ks * 16 + 12);  // b[4..7][1]
                uint32_t b[8][2] = {
                    {b0.x, b2.x}, {b0.y, b2.y}, {b0.z, b2.z}, {b0.w, b2.w},
                    {b1.x, b3.x}, {b1.y, b3.y}, {b1.z, b3.z}, {b1.w, b3.w}};
                uint32_t a[2][4];
                if (kss == 0) {
                    a[0][0] = av[0].x; a[0][1] = av[1].x; a[0][2] = av[0].y; a[0][3] = av[1].y;
                    a[1][0] = av[2].x; a[1][1] = av[3].x; a[1][2] = av[2].y; a[1][3] = av[3].y;
                } else {
                    a[0][0] = av[0].z; a[0][1] = av[1].z; a[0][2] = av[0].w; a[0][3] = av[1].w;
                    a[1][0] = av[2].z; a[1][1] = av[3].z; a[1][2] = av[2].w; a[1][3] = av[3].w;
                }
#pragma unroll
                for (int m = 0; m < 2; m++)
#pragma unroll
                    for (int j = 0; j < 8; j++) mma_tf32(c[m][j], a[m], b[j]);
            }
        }
        __syncthreads();
        if (has_next) {
            commit();
            __syncthreads();
        }
    }

    // ---- epilogue: store feat, compute el/er via in-register dot + quad reduce ----
    const int head = hp * 2 + warp_n;
    const int rh = r * 4 + head;
    const float* alp = attn_l + rh * HEAD_DIM;
    const float* arp = attn_r + rh * HEAD_DIM;

#pragma unroll
    for (int m = 0; m < 2; m++) {
        float pl0 = 0.f, pl1 = 0.f, pr0 = 0.f, pr1 = 0.f;
#pragma unroll
        for (int j = 0; j < 8; j++) {
            int col = j * 8 + 2 * t;
            float al0 = alp[col], al1 = alp[col + 1];
            float ar0 = arp[col], ar1 = arp[col + 1];
            pl0 += c[m][j][0] * al0 + c[m][j][1] * al1;
            pl1 += c[m][j][2] * al0 + c[m][j][3] * al1;
            pr0 += c[m][j][0] * ar0 + c[m][j][1] * ar1;
            pr1 += c[m][j][2] * ar0 + c[m][j][3] * ar1;
        }
        pl0 += __shfl_xor_sync(0xFFFFFFFFu, pl0, 1);
        pl0 += __shfl_xor_sync(0xFFFFFFFFu, pl0, 2);
        pl1 += __shfl_xor_sync(0xFFFFFFFFu, pl1, 1);
        pl1 += __shfl_xor_sync(0xFFFFFFFFu, pl1, 2);
        pr0 += __shfl_xor_sync(0xFFFFFFFFu, pr0, 1);
        pr0 += __shfl_xor_sync(0xFFFFFFFFu, pr0, 2);
        pr1 += __shfl_xor_sync(0xFFFFFFFFu, pr1, 1);
        pr1 += __shfl_xor_sync(0xFFFFFFFFu, pr1, 2);

        int row0 = rowBase + warp_m * 32 + m * 16 + g;
        int row1 = row0 + 8;
        if (t == 0) {
            if (row0 < N_NODES) {
                g_el[((size_t)r * N_NODES + row0) * 4 + head] = pl0;
                g_er[((size_t)r * N_NODES + row0) * 4 + head] = pr0;
            }
            if (row1 < N_NODES) {
                g_el[((size_t)r * N_NODES + row1) * 4 + head] = pl1;
                g_er[((size_t)r * N_NODES + row1) * 4 + head] = pr1;
            }
        }
#pragma unroll
        for (int j = 0; j < 8; j++) {
            int col = head * 64 + j * 8 + 2 * t;
            if (row0 < N_NODES)
                *(float2*)&g_feat[((size_t)r * N_NODES + row0) * 256 + col] =
                    make_float2(c[m][j][0], c[m][j][1]);
            if (row1 < N_NODES)
                *(float2*)&g_feat[((size_t)r * N_NODES + row1) * 256 + col] =
                    make_float2(c[m][j][2], c[m][j][3]);
        }
    }
}

// ---------------------------------------------------------------------------
// Kernel 2: fused bin scatter: each edge claims a slot in its destination's
// fixed-capacity bin via one atomic.
// ---------------------------------------------------------------------------
__global__ void scatter_kernel(const int* __restrict__ edge_dst) {
    int i = blockIdx.x * blockDim.x + threadIdx.x;
    if (i < N_EDGES) {
        int d = edge_dst[i];
        int pos = atomicAdd(&g_counts[d], 1);
        if (pos < CAP) g_perm[(size_t)d * CAP + pos] = i;
    }
}

// ---------------------------------------------------------------------------
// Kernel 3: fused segment softmax + weighted aggregation. Warp per node.
// Single pass: logits bounded (|e| < ~10) -> exp needs no max shift;
// softmax is shift-invariant so the result is identical.
// ---------------------------------------------------------------------------
__global__ __launch_bounds__(256) void agg_kernel(
    const int* __restrict__ edge_src,
    const int* __restrict__ edge_type,
    const float* __restrict__ h_bias,
    float* __restrict__ out)
{
    const int warp = threadIdx.x >> 5;
    const int lane = threadIdx.x & 31;
    const int node = blockIdx.x * 8 + warp;
    if (node >= N_NODES) return;

    const int cnt = min(g_counts[node], CAP);
    const size_t base = (size_t)node * CAP;

    float s0 = 0.f, s1 = 0.f, s2 = 0.f, s3 = 0.f;
    float acc[8];
#pragma unroll
    for (int q = 0; q < 8; q++) acc[q] = 0.f;
    const int hsel = lane >> 3;              // head of this lane's 8 output columns

    for (int b0 = 0; b0 < cnt; b0 += 32) {
        int j = b0 + lane;
        float w0 = 0.f, w1 = 0.f, w2 = 0.f, w3 = 0.f;
        int src = 0, et = 0;
        if (j < cnt) {
            int eid = g_perm[base + j];
            et = edge_type[eid];
            src = edge_src[eid];
            float4 el = *(const float4*)&g_el[((size_t)et * N_NODES + src) * 4];
            float4 er = *(const float4*)&g_er[((size_t)et * N_NODES + node) * 4];
            w0 = __expf(lrelu(el.x + er.x));
            w1 = __expf(lrelu(el.y + er.y));
            w2 = __expf(lrelu(el.z + er.z));
            w3 = __expf(lrelu(el.w + er.w));
            s0 += w0; s1 += w1; s2 += w2; s3 += w3;
        }
        int c2 = min(32, cnt - b0);
        for (int tt = 0; tt < c2; tt++) {
            int bsrc = __shfl_sync(0xFFFFFFFFu, src, tt);
            int bet  = __shfl_sync(0xFFFFFFFFu, et, tt);
            float bw0 = __shfl_sync(0xFFFFFFFFu, w0, tt);
            float bw1 = __shfl_sync(0xFFFFFFFFu, w1, tt);
            float bw2 = __shfl_sync(0xFFFFFFFFu, w2, tt);
            float bw3 = __shfl_sync(0xFFFFFFFFu, w3, tt);
            float ww = (hsel == 0) ? bw0 : (hsel == 1) ? bw1 : (hsel == 2) ? bw2 : bw3;
            const float4* fp =
                (const float4*)&g_feat[((size_t)bet * N_NODES + bsrc) * 256 + lane * 8];
            float4 v0 = fp[0], v1 = fp[1];
            acc[0] += ww * v0.x; acc[1] += ww * v0.y;
            acc[2] += ww * v0.z; acc[3] += ww * v0.w;
            acc[4] += ww * v1.x; acc[5] += ww * v1.y;
            acc[6] += ww * v1.z; acc[7] += ww * v1.w;
        }
    }
#pragma unroll
    for (int off = 16; off >= 1; off >>= 1) {
        s0 += __shfl_xor_sync(0xFFFFFFFFu, s0, off);
        s1 += __shfl_xor_sync(0xFFFFFFFFu, s1, off);
        s2 += __shfl_xor_sync(0xFFFFFFFFu, s2, off);
        s3 += __shfl_xor_sync(0xFFFFFFFFu, s3, off);
    }
    float sh = (hsel == 0) ? s0 : (hsel == 1) ? s1 : (hsel == 2) ? s2 : s3;
    float inv = (cnt > 0) ? (1.f / sh) : 0.f;

    int col = lane * 8;
    float4 o0, o1;
    o0.x = acc[0] * inv + h_bias[col + 0];
    o0.y = acc[1] * inv + h_bias[col + 1];
    o0.z = acc[2] * inv + h_bias[col + 2];
    o0.w = acc[3] * inv + h_bias[col + 3];
    o1.x = acc[4] * inv + h_bias[col + 4];
    o1.y = acc[5] * inv + h_bias[col + 5];
    o1.z = acc[6] * inv + h_bias[col + 6];
    o1.w = acc[7] * inv + h_bias[col + 7];
    *(float4*)&out[(size_t)node * 256 + col] = o0;
    *(float4*)&out[(size_t)node * 256 + col + 4] = o1;
}

// ---------------------------------------------------------------------------
extern "C" void kernel_launch(void* const* d_in, const int* in_sizes, int n_in,
                              void* d_out, int out_size) {
    const float* inputs  = (const float*)d_in[0];
    const float* conv_w  = (const float*)d_in[1];
    const float* attn_l  = (const float*)d_in[2];
    const float* attn_r  = (const float*)d_in[3];
    const float* h_bias  = (const float*)d_in[4];
    const int*   e_src   = (const int*)d_in[5];
    const int*   e_dst   = (const int*)d_in[6];
    const int*   e_type  = (const int*)d_in[7];
    float* out = (float*)d_out;

    static void* counts_ptr = nullptr;
    if (!counts_ptr) cudaGetSymbolAddress(&counts_ptr, g_counts);

    cudaMemsetAsync(counts_ptr, 0, N_NODES * sizeof(int));
    gemm_kernel<<<dim3((N_NODES + 127) / 128, N_RELS * 2), 256>>>(
        inputs, conv_w, attn_l, attn_r);
    scatter_kernel<<<(N_EDGES + 255) / 256, 256>>>(e_dst);
    agg_kernel<<<(N_NODES + 7) / 8, 256>>>(e_src, e_type, h_bias, out);
}

// round 12
// speedup vs baseline: 1.7280x; 1.7280x over previous
#include <cuda_runtime.h>
#include <cstdint>

#define N_NODES 30000
#define N_EDGES 480000
#define IN_FEAT 256
#define OUT_FEAT 256
#define N_RELS 8
#define N_HEADS 4
#define HEAD_DIM 64
#define CAP 64                      // max in-degree bin (Poisson(16): P(>=64) ~ 1e-18)

// -------- scratch (static device globals; no allocations allowed) --------
__device__ float g_feat[(size_t)N_RELS * N_NODES * OUT_FEAT];   // [r][n][h*64+d]
__device__ float g_el[N_RELS * N_NODES * N_HEADS];              // [r][n][h]
__device__ float g_er[N_RELS * N_NODES * N_HEADS];
__device__ int   g_counts[N_NODES];
__device__ int   g_perm[(size_t)N_NODES * CAP];

// pack two f32 into f16x2: low half = lo, high half = hi
__device__ __forceinline__ uint32_t pack_h2(float lo, float hi) {
    uint32_t u;
    asm("cvt.rn.f16x2.f32 %0, %1, %2;" : "=r"(u) : "f"(hi), "f"(lo));
    return u;
}

// mma m16n8k16 f16 inputs, f32 accumulate
__device__ __forceinline__ void mma_f16(float c[4], const uint32_t a[4], const uint32_t b[2]) {
    asm volatile(
        "mma.sync.aligned.m16n8k16.row.col.f32.f16.f16.f32 "
        "{%0,%1,%2,%3}, {%4,%5,%6,%7}, {%8,%9}, {%0,%1,%2,%3};"
        : "+f"(c[0]), "+f"(c[1]), "+f"(c[2]), "+f"(c[3])
        : "r"(a[0]), "r"(a[1]), "r"(a[2]), "r"(a[3]), "r"(b[0]), "r"(b[1]));
}

__device__ __forceinline__ float lrelu(float x) { return x >= 0.f ? x : 0.2f * x; }

// ---------------------------------------------------------------------------
// Kernel 1: GEMM  C[128 x 128] per CTA  (rowblock, rel*headpair)
//   feat_all[r][n][h*64+d] = sum_i inputs[n][i] * W[r][h][i][d]
// fp16 mma.sync m16n8k16 (fp16 significand == tf32 significand; fp32 accum).
// BM=128 BN=128 BK=32, 8 warps; warp = 32 rows x 64 cols (= one head).
// R2 structure: single smem buffer, register staging, two barriers per K-tile.
// smem holds k-packed f16x2: sAh[row][e] = (x[2e], x[2e+1]); entries t / t+4
// give the m16n8k16 fragments directly (same index shape as validated tf32).
// ---------------------------------------------------------------------------
__global__ __launch_bounds__(256, 2) void gemm_kernel(
    const float* __restrict__ A,        // [N_NODES, 256]
    const float* __restrict__ W,        // [8,4,256,64]
    const float* __restrict__ attn_l,   // [8,4,64]
    const float* __restrict__ attn_r)   // [8,4,64]
{
    __shared__ uint32_t sAh[128][20];   // 16 k-entries + pad4: frag banks 20g+t all distinct
    __shared__ uint32_t sBh[16][136];   // stride 136 -> banks 8t+g distinct (validated trick)

    const int r  = blockIdx.y >> 1;
    const int hp = blockIdx.y & 1;      // head pair: heads {2hp, 2hp+1}
    const int rowBase = blockIdx.x * 128;
    const int tid = threadIdx.x;
    const int warp = tid >> 5, lane = tid & 31;
    const int warp_m = warp >> 1;       // 0..3 (row group of 32)
    const int warp_n = warp & 1;        // 0..1 (head within pair)
    const int g = lane >> 2, t = lane & 3;
    const int cb = warp_n * 64;         // col base within 128-wide tile

    const float* Wbase = W + (size_t)(r * 4 + hp * 2) * IN_FEAT * HEAD_DIM;

    float c[2][8][4];
#pragma unroll
    for (int m = 0; m < 2; m++)
#pragma unroll
        for (int j = 0; j < 8; j++)
#pragma unroll
            for (int q = 0; q < 4; q++) c[m][j][q] = 0.f;

    // staging registers for the next K-tile
    float4 ar[4];
    float2 br2[8];

    auto ldA = [&](int k0) {
#pragma unroll
        for (int i = 0; i < 4; i++) {
            int idx = tid + i * 256;
            int row = idx >> 3, c4 = (idx & 7) << 2;
            int gr = rowBase + row;
            ar[i] = (gr < N_NODES)
                  ? *(const float4*)(A + (size_t)gr * IN_FEAT + k0 + c4)
                  : make_float4(0.f, 0.f, 0.f, 0.f);
        }
    };
    // B: load pairs of adjacent-k float2 so each thread can pack f16x2 along k
    auto ldB = [&](int k0) {
#pragma unroll
        for (int i = 0; i < 8; i++) {
            int pairIdx = tid + (i >> 1) * 256;   // 0..1023
            int kk = pairIdx >> 6;                // 0..15 (packed-k entry)
            int col2 = pairIdx & 63;              // float2 index over 128 cols
            int col = col2 * 2;
            int head = col >> 6, d = col & 63;
            int k = 2 * kk + (i & 1);
            br2[i] = *(const float2*)(Wbase + (size_t)head * (IN_FEAT * HEAD_DIM)
                                      + (size_t)(k0 + k) * HEAD_DIM + d);
        }
    };
    // commit staged registers to smem, converting fp32 -> packed f16x2
    auto commit = [&]() {
#pragma unroll
        for (int i = 0; i < 4; i++) {
            int idx = tid + i * 256;
            int row = idx >> 3, c4pos = idx & 7;  // float4 covers k = 4*c4pos..+3
            sAh[row][2 * c4pos]     = pack_h2(ar[i].x, ar[i].y);
            sAh[row][2 * c4pos + 1] = pack_h2(ar[i].z, ar[i].w);
        }
#pragma unroll
        for (int i = 0; i < 8; i += 2) {          // i: k even, i+1: k odd (same pairIdx)
            int pairIdx = tid + (i >> 1) * 256;
            int kk = pairIdx >> 6;
            int col2 = pairIdx & 63;
            sBh[kk][2 * col2]     = pack_h2(br2[i].x, br2[i + 1].x);
            sBh[kk][2 * col2 + 1] = pack_h2(br2[i].y, br2[i + 1].y);
        }
    };

    ldA(0); ldB(0);
    commit();
    __syncthreads();

    for (int k0 = 0; k0 < IN_FEAT; k0 += 32) {
        const bool has_next = (k0 + 32) < IN_FEAT;
        if (has_next) { ldA(k0 + 32); ldB(k0 + 32); }   // overlap with mma below

        // 2 k-steps of K=16 each
#pragma unroll
        for (int ks = 0; ks < 2; ks++) {
            const int kk = ks * 8;
            uint32_t a[2][4], b[8][2];
#pragma unroll
            for (int m = 0; m < 2; m++) {
                int row = warp_m * 32 + m * 16 + g;
                a[m][0] = sAh[row][kk + t];           // A[row][2t,2t+1]
                a[m][1] = sAh[row + 8][kk + t];
                a[m][2] = sAh[row][kk + t + 4];       // A[row][2t+8,2t+9]
                a[m][3] = sAh[row + 8][kk + t + 4];
            }
#pragma unroll
            for (int j = 0; j < 8; j++) {
                b[j][0] = sBh[kk + t][cb + j * 8 + g];      // B[2t..2t+1][col]
                b[j][1] = sBh[kk + t + 4][cb + j * 8 + g];  // B[2t+8..2t+9][col]
            }
#pragma unroll
            for (int m = 0; m < 2; m++)
#pragma unroll
                for (int j = 0; j < 8; j++) mma_f16(c[m][j], a[m], b[j]);
        }
        __syncthreads();
        if (has_next) {
            commit();
            __syncthreads();
        }
    }

    // ---- epilogue: store feat, compute el/er via in-register dot + quad reduce ----
    // (accumulator layout identical to the validated tf32 kernel)
    const int head = hp * 2 + warp_n;
    const int rh = r * 4 + head;
    const float* alp = attn_l + rh * HEAD_DIM;
    const float* arp = attn_r + rh * HEAD_DIM;

#pragma unroll
    for (int m = 0; m < 2; m++) {
        float pl0 = 0.f, pl1 = 0.f, pr0 = 0.f, pr1 = 0.f;
#pragma unroll
        for (int j = 0; j < 8; j++) {
            int col = j * 8 + 2 * t;
            float al0 = alp[col], al1 = alp[col + 1];
            float ar0 = arp[col], ar1 = arp[col + 1];
            pl0 += c[m][j][0] * al0 + c[m][j][1] * al1;
            pl1 += c[m][j][2] * al0 + c[m][j][3] * al1;
            pr0 += c[m][j][0] * ar0 + c[m][j][1] * ar1;
            pr1 += c[m][j][2] * ar0 + c[m][j][3] * ar1;
        }
        pl0 += __shfl_xor_sync(0xFFFFFFFFu, pl0, 1);
        pl0 += __shfl_xor_sync(0xFFFFFFFFu, pl0, 2);
        pl1 += __shfl_xor_sync(0xFFFFFFFFu, pl1, 1);
        pl1 += __shfl_xor_sync(0xFFFFFFFFu, pl1, 2);
        pr0 += __shfl_xor_sync(0xFFFFFFFFu, pr0, 1);
        pr0 += __shfl_xor_sync(0xFFFFFFFFu, pr0, 2);
        pr1 += __shfl_xor_sync(0xFFFFFFFFu, pr1, 1);
        pr1 += __shfl_xor_sync(0xFFFFFFFFu, pr1, 2);

        int row0 = rowBase + warp_m * 32 + m * 16 + g;
        int row1 = row0 + 8;
        if (t == 0) {
            if (row0 < N_NODES) {
                g_el[((size_t)r * N_NODES + row0) * 4 + head] = pl0;
                g_er[((size_t)r * N_NODES + row0) * 4 + head] = pr0;
            }
            if (row1 < N_NODES) {
                g_el[((size_t)r * N_NODES + row1) * 4 + head] = pl1;
                g_er[((size_t)r * N_NODES + row1) * 4 + head] = pr1;
            }
        }
#pragma unroll
        for (int j = 0; j < 8; j++) {
            int col = head * 64 + j * 8 + 2 * t;
            if (row0 < N_NODES)
                *(float2*)&g_feat[((size_t)r * N_NODES + row0) * 256 + col] =
                    make_float2(c[m][j][0], c[m][j][1]);
            if (row1 < N_NODES)
                *(float2*)&g_feat[((size_t)r * N_NODES + row1) * 256 + col] =
                    make_float2(c[m][j][2], c[m][j][3]);
        }
    }
}

// ---------------------------------------------------------------------------
// Kernel 2: fused bin scatter: each edge claims a slot in its destination's
// fixed-capacity bin via one atomic.
// ---------------------------------------------------------------------------
__global__ void scatter_kernel(const int* __restrict__ edge_dst) {
    int i = blockIdx.x * blockDim.x + threadIdx.x;
    if (i < N_EDGES) {
        int d = edge_dst[i];
        int pos = atomicAdd(&g_counts[d], 1);
        if (pos < CAP) g_perm[(size_t)d * CAP + pos] = i;
    }
}

// ---------------------------------------------------------------------------
// Kernel 3: fused segment softmax + weighted aggregation. Warp per node.
// Single pass: logits bounded (|e| < ~10) -> exp needs no max shift;
// softmax is shift-invariant so the result is identical.
// ---------------------------------------------------------------------------
__global__ __launch_bounds__(256) void agg_kernel(
    const int* __restrict__ edge_src,
    const int* __restrict__ edge_type,
    const float* __restrict__ h_bias,
    float* __restrict__ out)
{
    const int warp = threadIdx.x >> 5;
    const int lane = threadIdx.x & 31;
    const int node = blockIdx.x * 8 + warp;
    if (node >= N_NODES) return;

    const int cnt = min(g_counts[node], CAP);
    const size_t base = (size_t)node * CAP;

    float s0 = 0.f, s1 = 0.f, s2 = 0.f, s3 = 0.f;
    float acc[8];
#pragma unroll
    for (int q = 0; q < 8; q++) acc[q] = 0.f;
    const int hsel = lane >> 3;              // head of this lane's 8 output columns

    for (int b0 = 0; b0 < cnt; b0 += 32) {
        int j = b0 + lane;
        float w0 = 0.f, w1 = 0.f, w2 = 0.f, w3 = 0.f;
        int src = 0, et = 0;
        if (j < cnt) {
            int eid = g_perm[base + j];
            et = edge_type[eid];
            src = edge_src[eid];
            float4 el = *(const float4*)&g_el[((size_t)et * N_NODES + src) * 4];
            float4 er = *(const float4*)&g_er[((size_t)et * N_NODES + node) * 4];
            w0 = __expf(lrelu(el.x + er.x));
            w1 = __expf(lrelu(el.y + er.y));
            w2 = __expf(lrelu(el.z + er.z));
            w3 = __expf(lrelu(el.w + er.w));
            s0 += w0; s1 += w1; s2 += w2; s3 += w3;
        }
        int c2 = min(32, cnt - b0);
        for (int tt = 0; tt < c2; tt++) {
            int bsrc = __shfl_sync(0xFFFFFFFFu, src, tt);
            int bet  = __shfl_sync(0xFFFFFFFFu, et, tt);
            float bw0 = __shfl_sync(0xFFFFFFFFu, w0, tt);
            float bw1 = __shfl_sync(0xFFFFFFFFu, w1, tt);
            float bw2 = __shfl_sync(0xFFFFFFFFu, w2, tt);
            float bw3 = __shfl_sync(0xFFFFFFFFu, w3, tt);
            float ww = (hsel == 0) ? bw0 : (hsel == 1) ? bw1 : (hsel == 2) ? bw2 : bw3;
            const float4* fp =
                (const float4*)&g_feat[((size_t)bet * N_NODES + bsrc) * 256 + lane * 8];
            float4 v0 = fp[0], v1 = fp[1];
            acc[0] += ww * v0.x; acc[1] += ww * v0.y;
            acc[2] += ww * v0.z; acc[3] += ww * v0.w;
            acc[4] += ww * v1.x; acc[5] += ww * v1.y;
            acc[6] += ww * v1.z; acc[7] += ww * v1.w;
        }
    }
#pragma unroll
    for (int off = 16; off >= 1; off >>= 1) {
        s0 += __shfl_xor_sync(0xFFFFFFFFu, s0, off);
        s1 += __shfl_xor_sync(0xFFFFFFFFu, s1, off);
        s2 += __shfl_xor_sync(0xFFFFFFFFu, s2, off);
        s3 += __shfl_xor_sync(0xFFFFFFFFu, s3, off);
    }
    float sh = (hsel == 0) ? s0 : (hsel == 1) ? s1 : (hsel == 2) ? s2 : s3;
    float inv = (cnt > 0) ? (1.f / sh) : 0.f;

    int col = lane * 8;
    float4 o0, o1;
    o0.x = acc[0] * inv + h_bias[col + 0];
    o0.y = acc[1] * inv + h_bias[col + 1];
    o0.z = acc[2] * inv + h_bias[col + 2];
    o0.w = acc[3] * inv + h_bias[col + 3];
    o1.x = acc[4] * inv + h_bias[col + 4];
    o1.y = acc[5] * inv + h_bias[col + 5];
    o1.z = acc[6] * inv + h_bias[col + 6];
    o1.w = acc[7] * inv + h_bias[col + 7];
    *(float4*)&out[(size_t)node * 256 + col] = o0;
    *(float4*)&out[(size_t)node * 256 + col + 4] = o1;
}

// ---------------------------------------------------------------------------
extern "C" void kernel_launch(void* const* d_in, const int* in_sizes, int n_in,
                              void* d_out, int out_size) {
    const float* inputs  = (const float*)d_in[0];
    const float* conv_w  = (const float*)d_in[1];
    const float* attn_l  = (const float*)d_in[2];
    const float* attn_r  = (const float*)d_in[3];
    const float* h_bias  = (const float*)d_in[4];
    const int*   e_src   = (const int*)d_in[5];
    const int*   e_dst   = (const int*)d_in[6];
    const int*   e_type  = (const int*)d_in[7];
    float* out = (float*)d_out;

    static void* counts_ptr = nullptr;
    if (!counts_ptr) cudaGetSymbolAddress(&counts_ptr, g_counts);

    cudaMemsetAsync(counts_ptr, 0, N_NODES * sizeof(int));
    gemm_kernel<<<dim3((N_NODES + 127) / 128, N_RELS * 2), 256>>>(
        inputs, conv_w, attn_l, attn_r);
    scatter_kernel<<<(N_EDGES + 255) / 256, 256>>>(e_dst);
    agg_kernel<<<(N_NODES + 7) / 8, 256>>>(e_src, e_type, h_bias, out);
}

// round 13
// speedup vs baseline: 1.8351x; 1.0620x over previous
#include <cuda_runtime.h>
#include <cstdint>

#define N_NODES 30000
#define N_EDGES 480000
#define IN_FEAT 256
#define OUT_FEAT 256
#define N_RELS 8
#define N_HEADS 4
#define HEAD_DIM 64
#define CAP 64                      // max in-degree bin (Poisson(16): P(>=64) ~ 1e-18)

// -------- scratch (static device globals; no allocations allowed) --------
__device__ float g_feat[(size_t)N_RELS * N_NODES * OUT_FEAT];   // [r][n][h*64+d]
__device__ float g_el[N_RELS * N_NODES * N_HEADS];              // [r][n][h]
__device__ float g_er[N_RELS * N_NODES * N_HEADS];
__device__ int   g_counts[N_NODES];
__device__ int   g_perm[(size_t)N_NODES * CAP];

// pack two f32 into f16x2: low half = lo, high half = hi
__device__ __forceinline__ uint32_t pack_h2(float lo, float hi) {
    uint32_t u;
    asm("cvt.rn.f16x2.f32 %0, %1, %2;" : "=r"(u) : "f"(hi), "f"(lo));
    return u;
}

// mma m16n8k16 f16 inputs, f32 accumulate
__device__ __forceinline__ void mma_f16(float c[4], const uint32_t a[4], const uint32_t b[2]) {
    asm volatile(
        "mma.sync.aligned.m16n8k16.row.col.f32.f16.f16.f32 "
        "{%0,%1,%2,%3}, {%4,%5,%6,%7}, {%8,%9}, {%0,%1,%2,%3};"
        : "+f"(c[0]), "+f"(c[1]), "+f"(c[2]), "+f"(c[3])
        : "r"(a[0]), "r"(a[1]), "r"(a[2]), "r"(a[3]), "r"(b[0]), "r"(b[1]));
}

#define LDSM4(r0, r1, r2, r3, addr)                                           \
    asm volatile("ldmatrix.sync.aligned.m8n8.x4.shared.b16 {%0,%1,%2,%3}, [%4];" \
                 : "=r"(r0), "=r"(r1), "=r"(r2), "=r"(r3) : "r"(addr))

__device__ __forceinline__ float lrelu(float x) { return x >= 0.f ? x : 0.2f * x; }

// ---------------------------------------------------------------------------
// Kernel 1: GEMM  C[128 x 128] per CTA  (rowblock, rel*headpair)
//   feat_all[r][n][h*64+d] = sum_i inputs[n][i] * W[r][h][i][d]
// fp16 mma.sync m16n8k16, fragments loaded via ldmatrix.x4 (zero shuffles).
// BM=128 BN=128 BK=32, 8 warps; warp = 32 rows x 64 cols (= one head).
// Both A and B(transposed) in smem as [128 rows][20 words] k-packed f16x2:
// row stride 20 words -> ldmatrix 8-row segments tile all 32 banks perfectly.
// Hot loop per K-tile: 12 LDSM.x4 + 32 MMA (was 48 LDS.32 + 32 MMA).
// ---------------------------------------------------------------------------
__global__ __launch_bounds__(256, 2) void gemm_kernel(
    const float* __restrict__ A,        // [N_NODES, 256]
    const float* __restrict__ W,        // [8,4,256,64]
    const float* __restrict__ attn_l,   // [8,4,64]
    const float* __restrict__ attn_r)   // [8,4,64]
{
    __shared__ uint32_t sAh[128 * 20];  // [row][w]: w = k/2, pad 4 words
    __shared__ uint32_t sBh[128 * 20];  // [n][w]:   w = k/2, pad 4 words

    const int r  = blockIdx.y >> 1;
    const int hp = blockIdx.y & 1;      // head pair: heads {2hp, 2hp+1}
    const int rowBase = blockIdx.x * 128;
    const int tid = threadIdx.x;
    const int warp = tid >> 5, lane = tid & 31;
    const int warp_m = warp >> 1;       // 0..3 (row group of 32)
    const int warp_n = warp & 1;        // 0..1 (head within pair)
    const int g = lane >> 2, t = lane & 3;
    const int cb = warp_n * 64;         // B row (col) base within 128-wide tile

    const float* Wbase = W + (size_t)(r * 4 + hp * 2) * IN_FEAT * HEAD_DIM;

    float c[2][8][4];
#pragma unroll
    for (int m = 0; m < 2; m++)
#pragma unroll
        for (int j = 0; j < 8; j++)
#pragma unroll
            for (int q = 0; q < 4; q++) c[m][j][q] = 0.f;

    // staging registers for the next K-tile
    float4 ar[4];
    float  brf[16];

    // B loader: thread owns n-row (tid&127), half (tid>>7) selects k 0-15 / 16-31
    const int bn = tid & 127, bhalf = tid >> 7;
    const float* wcol = Wbase + (size_t)(bn >> 6) * (IN_FEAT * HEAD_DIM) + (bn & 63);

    auto ldA = [&](int k0) {
#pragma unroll
        for (int i = 0; i < 4; i++) {
            int idx = tid + i * 256;
            int row = idx >> 3, c4 = (idx & 7) << 2;
            int gr = rowBase + row;
            ar[i] = (gr < N_NODES)
                  ? *(const float4*)(A + (size_t)gr * IN_FEAT + k0 + c4)
                  : make_float4(0.f, 0.f, 0.f, 0.f);
        }
    };
    auto ldB = [&](int k0) {
#pragma unroll
        for (int w = 0; w < 8; w++) {
            int k = k0 + (bhalf * 8 + w) * 2;
            brf[2 * w]     = wcol[(size_t)k * HEAD_DIM];
            brf[2 * w + 1] = wcol[(size_t)(k + 1) * HEAD_DIM];
        }
    };
    auto commit = [&]() {
#pragma unroll
        for (int i = 0; i < 4; i++) {
            int idx = tid + i * 256;
            int row = idx >> 3, c4pos = idx & 7;  // float4 covers k = 4*c4pos..+3
            sAh[row * 20 + 2 * c4pos]     = pack_h2(ar[i].x, ar[i].y);
            sAh[row * 20 + 2 * c4pos + 1] = pack_h2(ar[i].z, ar[i].w);
        }
#pragma unroll
        for (int w = 0; w < 8; w++)
            sBh[bn * 20 + bhalf * 8 + w] = pack_h2(brf[2 * w], brf[2 * w + 1]);
    };

    ldA(0); ldB(0);
    commit();
    __syncthreads();

    // per-lane ldmatrix addresses (bytes)
    uint32_t sA_b = (uint32_t)__cvta_generic_to_shared(sAh);
    uint32_t sB_b = (uint32_t)__cvta_generic_to_shared(sBh);
    // A: lanes 0-15 -> rows +0..15 (k-lo), lanes 16-31 -> same rows (k-hi word+4)
    uint32_t aAddr = sA_b + (((warp_m * 32 + (lane & 15)) * 20 + ((lane >> 4) << 2)) << 2);
    // B: lanes 0-7 rows+0..7 w+0 | 8-15 rows+0..7 w+4 | 16-23 rows+8.. w+0 | 24-31 w+4
    uint32_t bAddr = sB_b + (((cb + ((lane >> 4) << 3) + (lane & 7)) * 20
                              + (((lane >> 3) & 1) << 2)) << 2);

    for (int k0 = 0; k0 < IN_FEAT; k0 += 32) {
        const bool has_next = (k0 + 32) < IN_FEAT;
        if (has_next) { ldA(k0 + 32); ldB(k0 + 32); }   // overlap with mma below

#pragma unroll
        for (int ks = 0; ks < 2; ks++) {
            const uint32_t ko = (ks * 8) << 2;          // +8 words per ks
            uint32_t a[2][4], b[8][2];
            LDSM4(a[0][0], a[0][1], a[0][2], a[0][3], aAddr + ko);
            LDSM4(a[1][0], a[1][1], a[1][2], a[1][3], aAddr + ko + (16 * 20 << 2));
#pragma unroll
            for (int j2 = 0; j2 < 4; j2++) {
                LDSM4(b[2 * j2][0], b[2 * j2][1], b[2 * j2 + 1][0], b[2 * j2 + 1][1],
                      bAddr + ko + ((16 * 20 * j2) << 2));
            }
#pragma unroll
            for (int m = 0; m < 2; m++)
#pragma unroll
                for (int j = 0; j < 8; j++) mma_f16(c[m][j], a[m], b[j]);
        }
        __syncthreads();
        if (has_next) {
            commit();
            __syncthreads();
        }
    }

    // ---- epilogue: store feat, compute el/er via in-register dot + quad reduce ----
    // (accumulator layout identical to validated R12 kernel)
    const int head = hp * 2 + warp_n;
    const int rh = r * 4 + head;
    const float* alp = attn_l + rh * HEAD_DIM;
    const float* arp = attn_r + rh * HEAD_DIM;

#pragma unroll
    for (int m = 0; m < 2; m++) {
        float pl0 = 0.f, pl1 = 0.f, pr0 = 0.f, pr1 = 0.f;
#pragma unroll
        for (int j = 0; j < 8; j++) {
            int col = j * 8 + 2 * t;
            float al0 = alp[col], al1 = alp[col + 1];
            float ar0 = arp[col], ar1 = arp[col + 1];
            pl0 += c[m][j][0] * al0 + c[m][j][1] * al1;
            pl1 += c[m][j][2] * al0 + c[m][j][3] * al1;
            pr0 += c[m][j][0] * ar0 + c[m][j][1] * ar1;
            pr1 += c[m][j][2] * ar0 + c[m][j][3] * ar1;
        }
        pl0 += __shfl_xor_sync(0xFFFFFFFFu, pl0, 1);
        pl0 += __shfl_xor_sync(0xFFFFFFFFu, pl0, 2);
        pl1 += __shfl_xor_sync(0xFFFFFFFFu, pl1, 1);
        pl1 += __shfl_xor_sync(0xFFFFFFFFu, pl1, 2);
        pr0 += __shfl_xor_sync(0xFFFFFFFFu, pr0, 1);
        pr0 += __shfl_xor_sync(0xFFFFFFFFu, pr0, 2);
        pr1 += __shfl_xor_sync(0xFFFFFFFFu, pr1, 1);
        pr1 += __shfl_xor_sync(0xFFFFFFFFu, pr1, 2);

        int row0 = rowBase + warp_m * 32 + m * 16 + g;
        int row1 = row0 + 8;
        if (t == 0) {
            if (row0 < N_NODES) {
                g_el[((size_t)r * N_NODES + row0) * 4 + head] = pl0;
                g_er[((size_t)r * N_NODES + row0) * 4 + head] = pr0;
            }
            if (row1 < N_NODES) {
                g_el[((size_t)r * N_NODES + row1) * 4 + head] = pl1;
                g_er[((size_t)r * N_NODES + row1) * 4 + head] = pr1;
            }
        }
#pragma unroll
        for (int j = 0; j < 8; j++) {
            int col = head * 64 + j * 8 + 2 * t;
            if (row0 < N_NODES)
                *(float2*)&g_feat[((size_t)r * N_NODES + row0) * 256 + col] =
                    make_float2(c[m][j][0], c[m][j][1]);
            if (row1 < N_NODES)
                *(float2*)&g_feat[((size_t)r * N_NODES + row1) * 256 + col] =
                    make_float2(c[m][j][2], c[m][j][3]);
        }
    }
}

// ---------------------------------------------------------------------------
// Kernel 2: fused bin scatter: each edge claims a slot in its destination's
// fixed-capacity bin via one atomic.
// ---------------------------------------------------------------------------
__global__ void scatter_kernel(const int* __restrict__ edge_dst) {
    int i = blockIdx.x * blockDim.x + threadIdx.x;
    if (i < N_EDGES) {
        int d = edge_dst[i];
        int pos = atomicAdd(&g_counts[d], 1);
        if (pos < CAP) g_perm[(size_t)d * CAP + pos] = i;
    }
}

// ---------------------------------------------------------------------------
// Kernel 3: fused segment softmax + weighted aggregation. Warp per node.
// Single pass: logits bounded (|e| < ~10) -> exp needs no max shift;
// softmax is shift-invariant so the result is identical.
// ---------------------------------------------------------------------------
__global__ __launch_bounds__(256) void agg_kernel(
    const int* __restrict__ edge_src,
    const int* __restrict__ edge_type,
    const float* __restrict__ h_bias,
    float* __restrict__ out)
{
    const int warp = threadIdx.x >> 5;
    const int lane = threadIdx.x & 31;
    const int node = blockIdx.x * 8 + warp;
    if (node >= N_NODES) return;

    const int cnt = min(g_counts[node], CAP);
    const size_t base = (size_t)node * CAP;

    float s0 = 0.f, s1 = 0.f, s2 = 0.f, s3 = 0.f;
    float acc[8];
#pragma unroll
    for (int q = 0; q < 8; q++) acc[q] = 0.f;
    const int hsel = lane >> 3;              // head of this lane's 8 output columns

    for (int b0 = 0; b0 < cnt; b0 += 32) {
        int j = b0 + lane;
        float w0 = 0.f, w1 = 0.f, w2 = 0.f, w3 = 0.f;
        int src = 0, et = 0;
        if (j < cnt) {
            int eid = g_perm[base + j];
            et = edge_type[eid];
            src = edge_src[eid];
            float4 el = *(const float4*)&g_el[((size_t)et * N_NODES + src) * 4];
            float4 er = *(const float4*)&g_er[((size_t)et * N_NODES + node) * 4];
            w0 = __expf(lrelu(el.x + er.x));
            w1 = __expf(lrelu(el.y + er.y));
            w2 = __expf(lrelu(el.z + er.z));
            w3 = __expf(lrelu(el.w + er.w));
            s0 += w0; s1 += w1; s2 += w2; s3 += w3;
        }
        int c2 = min(32, cnt - b0);
        for (int tt = 0; tt < c2; tt++) {
            int bsrc = __shfl_sync(0xFFFFFFFFu, src, tt);
            int bet  = __shfl_sync(0xFFFFFFFFu, et, tt);
            float bw0 = __shfl_sync(0xFFFFFFFFu, w0, tt);
            float bw1 = __shfl_sync(0xFFFFFFFFu, w1, tt);
            float bw2 = __shfl_sync(0xFFFFFFFFu, w2, tt);
            float bw3 = __shfl_sync(0xFFFFFFFFu, w3, tt);
            float ww = (hsel == 0) ? bw0 : (hsel == 1) ? bw1 : (hsel == 2) ? bw2 : bw3;
            const float4* fp =
                (const float4*)&g_feat[((size_t)bet * N_NODES + bsrc) * 256 + lane * 8];
            float4 v0 = fp[0], v1 = fp[1];
            acc[0] += ww * v0.x; acc[1] += ww * v0.y;
            acc[2] += ww * v0.z; acc[3] += ww * v0.w;
            acc[4] += ww * v1.x; acc[5] += ww * v1.y;
            acc[6] += ww * v1.z; acc[7] += ww * v1.w;
        }
    }
#pragma unroll
    for (int off = 16; off >= 1; off >>= 1) {
        s0 += __shfl_xor_sync(0xFFFFFFFFu, s0, off);
        s1 += __shfl_xor_sync(0xFFFFFFFFu, s1, off);
        s2 += __shfl_xor_sync(0xFFFFFFFFu, s2, off);
        s3 += __shfl_xor_sync(0xFFFFFFFFu, s3, off);
    }
    float sh = (hsel == 0) ? s0 : (hsel == 1) ? s1 : (hsel == 2) ? s2 : s3;
    float inv = (cnt > 0) ? (1.f / sh) : 0.f;

    int col = lane * 8;
    float4 o0, o1;
    o0.x = acc[0] * inv + h_bias[col + 0];
    o0.y = acc[1] * inv + h_bias[col + 1];
    o0.z = acc[2] * inv + h_bias[col + 2];
    o0.w = acc[3] * inv + h_bias[col + 3];
    o1.x = acc[4] * inv + h_bias[col + 4];
    o1.y = acc[5] * inv + h_bias[col + 5];
    o1.z = acc[6] * inv + h_bias[col + 6];
    o1.w = acc[7] * inv + h_bias[col + 7];
    *(float4*)&out[(size_t)node * 256 + col] = o0;
    *(float4*)&out[(size_t)node * 256 + col + 4] = o1;
}

// ---------------------------------------------------------------------------
extern "C" void kernel_launch(void* const* d_in, const int* in_sizes, int n_in,
                              void* d_out, int out_size) {
    const float* inputs  = (const float*)d_in[0];
    const float* conv_w  = (const float*)d_in[1];
    const float* attn_l  = (const float*)d_in[2];
    const float* attn_r  = (const float*)d_in[3];
    const float* h_bias  = (const float*)d_in[4];
    const int*   e_src   = (const int*)d_in[5];
    const int*   e_dst   = (const int*)d_in[6];
    const int*   e_type  = (const int*)d_in[7];
    float* out = (float*)d_out;

    static void* counts_ptr = nullptr;
    if (!counts_ptr) cudaGetSymbolAddress(&counts_ptr, g_counts);

    cudaMemsetAsync(counts_ptr, 0, N_NODES * sizeof(int));
    gemm_kernel<<<dim3((N_NODES + 127) / 128, N_RELS * 2), 256>>>(
        inputs, conv_w, attn_l, attn_r);
    scatter_kernel<<<(N_EDGES + 255) / 256, 256>>>(e_dst);
    agg_kernel<<<(N_NODES + 7) / 8, 256>>>(e_src, e_type, h_bias, out);
}

// round 15
// speedup vs baseline: 2.0241x; 1.1030x over previous
#include <cuda_runtime.h>
#include <cstdint>
#include <cuda_fp16.h>

#define N_NODES 30000
#define N_EDGES 480000
#define IN_FEAT 256
#define OUT_FEAT 256
#define N_RELS 8
#define N_HEADS 4
#define HEAD_DIM 64
#define CAP 64                      // max in-degree bin (Poisson(16): P(>=64) ~ 1e-18)

// -------- scratch (static device globals; no allocations allowed) --------
__device__ uint32_t g_feat[(size_t)N_RELS * N_NODES * 128];     // f16x2: [r][n][word], word=col/2
__device__ float g_el[N_RELS * N_NODES * N_HEADS];              // [r][n][h]
__device__ float g_er[N_RELS * N_NODES * N_HEADS];
__device__ int   g_counts[N_NODES];
__device__ int   g_perm[(size_t)N_NODES * CAP];

// pack two f32 into f16x2: low half = lo, high half = hi
__device__ __forceinline__ uint32_t pack_h2(float lo, float hi) {
    uint32_t u;
    asm("cvt.rn.f16x2.f32 %0, %1, %2;" : "=r"(u) : "f"(hi), "f"(lo));
    return u;
}

// mma m16n8k16 f16 inputs, f32 accumulate
__device__ __forceinline__ void mma_f16(float c[4], const uint32_t a[4], const uint32_t b[2]) {
    asm volatile(
        "mma.sync.aligned.m16n8k16.row.col.f32.f16.f16.f32 "
        "{%0,%1,%2,%3}, {%4,%5,%6,%7}, {%8,%9}, {%0,%1,%2,%3};"
        : "+f"(c[0]), "+f"(c[1]), "+f"(c[2]), "+f"(c[3])
        : "r"(a[0]), "r"(a[1]), "r"(a[2]), "r"(a[3]), "r"(b[0]), "r"(b[1]));
}

#define LDSM4(r0, r1, r2, r3, addr)                                           \
    asm volatile("ldmatrix.sync.aligned.m8n8.x4.shared.b16 {%0,%1,%2,%3}, [%4];" \
                 : "=r"(r0), "=r"(r1), "=r"(r2), "=r"(r3) : "r"(addr))

__device__ __forceinline__ float lrelu(float x) { return x >= 0.f ? x : 0.2f * x; }

// ---------------------------------------------------------------------------
// Kernel 1: GEMM  C[128 x 128] per CTA  (rowblock, rel*headpair)
//   feat_all[r][n][h*64+d] = sum_i inputs[n][i] * W[r][h][i][d]
// fp16 mma.sync m16n8k16, ldmatrix fragment loads (validated R13 mainloop).
// Epilogue: el/er dots from f32 accumulators (unchanged precision); feat
// stored as packed f16x2 (halves write traffic + downstream gather traffic).
// ---------------------------------------------------------------------------
__global__ __launch_bounds__(256, 2) void gemm_kernel(
    const float* __restrict__ A,        // [N_NODES, 256]
    const float* __restrict__ W,        // [8,4,256,64]
    const float* __restrict__ attn_l,   // [8,4,64]
    const float* __restrict__ attn_r)   // [8,4,64]
{
    __shared__ uint32_t sAh[128 * 20];  // [row][w]: w = k/2, pad 4 words
    __shared__ uint32_t sBh[128 * 20];  // [n][w]:   w = k/2, pad 4 words

    const int r  = blockIdx.y >> 1;
    const int hp = blockIdx.y & 1;      // head pair: heads {2hp, 2hp+1}
    const int rowBase = blockIdx.x * 128;
    const int tid = threadIdx.x;
    const int warp = tid >> 5, lane = tid & 31;
    const int warp_m = warp >> 1;       // 0..3 (row group of 32)
    const int warp_n = warp & 1;        // 0..1 (head within pair)
    const int g = lane >> 2, t = lane & 3;
    const int cb = warp_n * 64;         // B row (col) base within 128-wide tile

    const float* Wbase = W + (size_t)(r * 4 + hp * 2) * IN_FEAT * HEAD_DIM;

    float c[2][8][4];
#pragma unroll
    for (int m = 0; m < 2; m++)
#pragma unroll
        for (int j = 0; j < 8; j++)
#pragma unroll
            for (int q = 0; q < 4; q++) c[m][j][q] = 0.f;

    // staging registers for the next K-tile
    float4 ar[4];
    float  brf[16];

    // B loader: thread owns n-row (tid&127), half (tid>>7) selects k 0-15 / 16-31
    const int bn = tid & 127, bhalf = tid >> 7;
    const float* wcol = Wbase + (size_t)(bn >> 6) * (IN_FEAT * HEAD_DIM) + (bn & 63);

    auto ldA = [&](int k0) {
#pragma unroll
        for (int i = 0; i < 4; i++) {
            int idx = tid + i * 256;
            int row = idx >> 3, c4 = (idx & 7) << 2;
            int gr = rowBase + row;
            ar[i] = (gr < N_NODES)
                  ? *(const float4*)(A + (size_t)gr * IN_FEAT + k0 + c4)
                  : make_float4(0.f, 0.f, 0.f, 0.f);
        }
    };
    auto ldB = [&](int k0) {
#pragma unroll
        for (int w = 0; w < 8; w++) {
            int k = k0 + (bhalf * 8 + w) * 2;
            brf[2 * w]     = wcol[(size_t)k * HEAD_DIM];
            brf[2 * w + 1] = wcol[(size_t)(k + 1) * HEAD_DIM];
        }
    };
    auto commit = [&]() {
#pragma unroll
        for (int i = 0; i < 4; i++) {
            int idx = tid + i * 256;
            int row = idx >> 3, c4pos = idx & 7;  // float4 covers k = 4*c4pos..+3
            sAh[row * 20 + 2 * c4pos]     = pack_h2(ar[i].x, ar[i].y);
            sAh[row * 20 + 2 * c4pos + 1] = pack_h2(ar[i].z, ar[i].w);
        }
#pragma unroll
        for (int w = 0; w < 8; w++)
            sBh[bn * 20 + bhalf * 8 + w] = pack_h2(brf[2 * w], brf[2 * w + 1]);
    };

    ldA(0); ldB(0);
    commit();
    __syncthreads();

    // per-lane ldmatrix addresses (bytes)
    uint32_t sA_b = (uint32_t)__cvta_generic_to_shared(sAh);
    uint32_t sB_b = (uint32_t)__cvta_generic_to_shared(sBh);
    // A: lanes 0-15 -> rows +0..15 (k-lo), lanes 16-31 -> same rows (k-hi word+4)
    uint32_t aAddr = sA_b + (((warp_m * 32 + (lane & 15)) * 20 + ((lane >> 4) << 2)) << 2);
    // B: lanes 0-7 rows+0..7 w+0 | 8-15 rows+0..7 w+4 | 16-23 rows+8.. w+0 | 24-31 w+4
    uint32_t bAddr = sB_b + (((cb + ((lane >> 4) << 3) + (lane & 7)) * 20
                              + (((lane >> 3) & 1) << 2)) << 2);

    for (int k0 = 0; k0 < IN_FEAT; k0 += 32) {
        const bool has_next = (k0 + 32) < IN_FEAT;
        if (has_next) { ldA(k0 + 32); ldB(k0 + 32); }   // overlap with mma below

#pragma unroll
        for (int ks = 0; ks < 2; ks++) {
            const uint32_t ko = (ks * 8) << 2;          // +8 words per ks
            uint32_t a[2][4], b[8][2];
            LDSM4(a[0][0], a[0][1], a[0][2], a[0][3], aAddr + ko);
            LDSM4(a[1][0], a[1][1], a[1][2], a[1][3], aAddr + ko + (16 * 20 << 2));
#pragma unroll
            for (int j2 = 0; j2 < 4; j2++) {
                LDSM4(b[2 * j2][0], b[2 * j2][1], b[2 * j2 + 1][0], b[2 * j2 + 1][1],
                      bAddr + ko + ((16 * 20 * j2) << 2));
            }
#pragma unroll
            for (int m = 0; m < 2; m++)
#pragma unroll
                for (int j = 0; j < 8; j++) mma_f16(c[m][j], a[m], b[j]);
        }
        __syncthreads();
        if (has_next) {
            commit();
            __syncthreads();
        }
    }

    // ---- epilogue: el/er dots from f32 accums, feat stored as f16x2 ----
    const int head = hp * 2 + warp_n;
    const int rh = r * 4 + head;
    const float* alp = attn_l + rh * HEAD_DIM;
    const float* arp = attn_r + rh * HEAD_DIM;

#pragma unroll
    for (int m = 0; m < 2; m++) {
        float pl0 = 0.f, pl1 = 0.f, pr0 = 0.f, pr1 = 0.f;
#pragma unroll
        for (int j = 0; j < 8; j++) {
            int col = j * 8 + 2 * t;
            float al0 = alp[col], al1 = alp[col + 1];
            float ar0 = arp[col], ar1 = arp[col + 1];
            pl0 += c[m][j][0] * al0 + c[m][j][1] * al1;
            pl1 += c[m][j][2] * al0 + c[m][j][3] * al1;
            pr0 += c[m][j][0] * ar0 + c[m][j][1] * ar1;
            pr1 += c[m][j][2] * ar0 + c[m][j][3] * ar1;
        }
        pl0 += __shfl_xor_sync(0xFFFFFFFFu, pl0, 1);
        pl0 += __shfl_xor_sync(0xFFFFFFFFu, pl0, 2);
        pl1 += __shfl_xor_sync(0xFFFFFFFFu, pl1, 1);
        pl1 += __shfl_xor_sync(0xFFFFFFFFu, pl1, 2);
        pr0 += __shfl_xor_sync(0xFFFFFFFFu, pr0, 1);
        pr0 += __shfl_xor_sync(0xFFFFFFFFu, pr0, 2);
        pr1 += __shfl_xor_sync(0xFFFFFFFFu, pr1, 1);
        pr1 += __shfl_xor_sync(0xFFFFFFFFu, pr1, 2);

        int row0 = rowBase + warp_m * 32 + m * 16 + g;
        int row1 = row0 + 8;
        if (t == 0) {
            if (row0 < N_NODES) {
                g_el[((size_t)r * N_NODES + row0) * 4 + head] = pl0;
                g_er[((size_t)r * N_NODES + row0) * 4 + head] = pr0;
            }
            if (row1 < N_NODES) {
                g_el[((size_t)r * N_NODES + row1) * 4 + head] = pl1;
                g_er[((size_t)r * N_NODES + row1) * 4 + head] = pr1;
            }
        }
#pragma unroll
        for (int j = 0; j < 8; j++) {
            int word = head * 32 + j * 4 + t;        // col/2, col = head*64+j*8+2t
            if (row0 < N_NODES)
                g_feat[((size_t)r * N_NODES + row0) * 128 + word] =
                    pack_h2(c[m][j][0], c[m][j][1]);
            if (row1 < N_NODES)
                g_feat[((size_t)r * N_NODES + row1) * 128 + word] =
                    pack_h2(c[m][j][2], c[m][j][3]);
        }
    }
}

// ---------------------------------------------------------------------------
// Kernel 2: fused bin scatter: each edge claims a slot in its destination's
// fixed-capacity bin via one atomic.
// ---------------------------------------------------------------------------
__global__ void scatter_kernel(const int* __restrict__ edge_dst) {
    int i = blockIdx.x * blockDim.x + threadIdx.x;
    if (i < N_EDGES) {
        int d = edge_dst[i];
        int pos = atomicAdd(&g_counts[d], 1);
        if (pos < CAP) g_perm[(size_t)d * CAP + pos] = i;
    }
}

// ---------------------------------------------------------------------------
// Kernel 3: fused segment softmax + weighted aggregation. Warp per node.
// feat rows are f16x2-packed (512 B/row): one uint4 gather per lane per edge.
// Accumulation in f32. Single pass (no max shift; softmax shift-invariant).
// ---------------------------------------------------------------------------
__global__ __launch_bounds__(256) void agg_kernel(
    const int* __restrict__ edge_src,
    const int* __restrict__ edge_type,
    const float* __restrict__ h_bias,
    float* __restrict__ out)
{
    const int warp = threadIdx.x >> 5;
    const int lane = threadIdx.x & 31;
    const int node = blockIdx.x * 8 + warp;
    if (node >= N_NODES) return;

    const int cnt = min(g_counts[node], CAP);
    const size_t base = (size_t)node * CAP;

    float s0 = 0.f, s1 = 0.f, s2 = 0.f, s3 = 0.f;
    float acc[8];
#pragma unroll
    for (int q = 0; q < 8; q++) acc[q] = 0.f;
    const int hsel = lane >> 3;              // head of this lane's 8 output columns

    for (int b0 = 0; b0 < cnt; b0 += 32) {
        int j = b0 + lane;
        float w0 = 0.f, w1 = 0.f, w2 = 0.f, w3 = 0.f;
        int src = 0, et = 0;
        if (j < cnt) {
            int eid = g_perm[base + j];
            et = edge_type[eid];
            src = edge_src[eid];
            float4 el = *(const float4*)&g_el[((size_t)et * N_NODES + src) * 4];
            float4 er = *(const float4*)&g_er[((size_t)et * N_NODES + node) * 4];
            w0 = __expf(lrelu(el.x + er.x));
            w1 = __expf(lrelu(el.y + er.y));
            w2 = __expf(lrelu(el.z + er.z));
            w3 = __expf(lrelu(el.w + er.w));
            s0 += w0; s1 += w1; s2 += w2; s3 += w3;
        }
        int c2 = min(32, cnt - b0);
        for (int tt = 0; tt < c2; tt++) {
            int bsrc = __shfl_sync(0xFFFFFFFFu, src, tt);
            int bet  = __shfl_sync(0xFFFFFFFFu, et, tt);
            float bw0 = __shfl_sync(0xFFFFFFFFu, w0, tt);
            float bw1 = __shfl_sync(0xFFFFFFFFu, w1, tt);
            float bw2 = __shfl_sync(0xFFFFFFFFu, w2, tt);
            float bw3 = __shfl_sync(0xFFFFFFFFu, w3, tt);
            float ww = (hsel == 0) ? bw0 : (hsel == 1) ? bw1 : (hsel == 2) ? bw2 : bw3;
            // lane's 8 cols = 4 packed words = one uint4
            const uint4* fp =
                (const uint4*)&g_feat[((size_t)bet * N_NODES + bsrc) * 128 + lane * 4];
            uint4 v = *fp;
            float2 f0 = __half22float2(*(const __half2*)&v.x);
            float2 f1 = __half22float2(*(const __half2*)&v.y);
            float2 f2 = __half22float2(*(const __half2*)&v.z);
            float2 f3 = __half22float2(*(const __half2*)&v.w);
            acc[0] += ww * f0.x; acc[1] += ww * f0.y;
            acc[2] += ww * f1.x; acc[3] += ww * f1.y;
            acc[4] += ww * f2.x; acc[5] += ww * f2.y;
            acc[6] += ww * f3.x; acc[7] += ww * f3.y;
        }
    }
#pragma unroll
    for (int off = 16; off >= 1; off >>= 1) {
        s0 += __shfl_xor_sync(0xFFFFFFFFu, s0, off);
        s1 += __shfl_xor_sync(0xFFFFFFFFu, s1, off);
        s2 += __shfl_xor_sync(0xFFFFFFFFu, s2, off);
        s3 += __shfl_xor_sync(0xFFFFFFFFu, s3, off);
    }
    float sh = (hsel == 0) ? s0 : (hsel == 1) ? s1 : (hsel == 2) ? s2 : s3;
    float inv = (cnt > 0) ? (1.f / sh) : 0.f;

    int col = lane * 8;
    float4 o0, o1;
    o0.x = acc[0] * inv + h_bias[col + 0];
    o0.y = acc[1] * inv + h_bias[col + 1];
    o0.z = acc[2] * inv + h_bias[col + 2];
    o0.w = acc[3] * inv + h_bias[col + 3];
    o1.x = acc[4] * inv + h_bias[col + 4];
    o1.y = acc[5] * inv + h_bias[col + 5];
    o1.z = acc[6] * inv + h_bias[col + 6];
    o1.w = acc[7] * inv + h_bias[col + 7];
    *(float4*)&out[(size_t)node * 256 + col] = o0;
    *(float4*)&out[(size_t)node * 256 + col + 4] = o1;
}

// ---------------------------------------------------------------------------
extern "C" void kernel_launch(void* const* d_in, const int* in_sizes, int n_in,
                              void* d_out, int out_size) {
    const float* inputs  = (const float*)d_in[0];
    const float* conv_w  = (const float*)d_in[1];
    const float* attn_l  = (const float*)d_in[2];
    const float* attn_r  = (const float*)d_in[3];
    const float* h_bias  = (const float*)d_in[4];
    const int*   e_src   = (const int*)d_in[5];
    const int*   e_dst   = (const int*)d_in[6];
    const int*   e_type  = (const int*)d_in[7];
    float* out = (float*)d_out;

    static void* counts_ptr = nullptr;
    if (!counts_ptr) cudaGetSymbolAddress(&counts_ptr, g_counts);

    cudaMemsetAsync(counts_ptr, 0, N_NODES * sizeof(int));
    gemm_kernel<<<dim3((N_NODES + 127) / 128, N_RELS * 2), 256>>>(
        inputs, conv_w, attn_l, attn_r);
    scatter_kernel<<<(N_EDGES + 255) / 256, 256>>>(e_dst);
    agg_kernel<<<(N_NODES + 7) / 8, 256>>>(e_src, e_type, h_bias, out);
}